// round 15
// baseline (speedup 1.0000x reference)
#include <cuda_runtime.h>
#include <cuda_bf16.h>
#include <cuda_fp16.h>

namespace {
constexpr int B_ = 8, V_ = 64, T_ = 256, T1_ = 257, D_ = 256, H_ = 8, DH_ = 32;
constexpr float EPS = 1e-5f;
constexpr int LDA = 264;                 // f16 elems per sA row (528B)
constexpr int LDW = 40;                  // f16 elems per K=32 weight-chunk row (80B)
// k_main dynamic smem layout (bytes)
constexpr int OFF_W0 = 128 * LDA * 2;                // sA = 67584
constexpr int OFF_W1 = OFF_W0 + 256 * LDW * 2;       // +20480
constexpr int SM_MAIN = OFF_W1 + 256 * LDW * 2;      // 108544 -> 2 blocks/SM
// k_qkattn dynamic smem layout
constexpr int QA_X  = 0;                             // bf16 [64][264]
constexpr int QA_Y  = 64 * 264 * 2;                  // bf16 [64][264]
constexpr int QA_Q  = QA_Y + 64 * 264 * 2;           // f32 [64][36]
constexpr int QA_K  = QA_Q + 64 * 36 * 4;            // f32 [64][36]
constexpr int QA_S  = QA_K + 64 * 36 * 4;            // f32 [64][65]
constexpr int SM_QA = QA_S + 64 * 65 * 4;            // 102656
}

// ---------------- scratch (device globals) ----------------------------------
__device__ __half g_wv16[256 * 256];           // f16 Wv
__device__ __half g_wp16[256 * 256];           // f16 Wp
__device__ __nv_bfloat16 g_xn0[512 * 256];     // LN(x[:,:,0])
__device__ __nv_bfloat16 g_xbar[512 * 256];    // masked mean of LN(x)
__device__ __half g_attn[8 * 8 * 64 * 64];
__device__ unsigned g_det[64];                 // mask-probe partials

__device__ __forceinline__ float warp_sum(float v) {
#pragma unroll
    for (int o = 16; o; o >>= 1) v += __shfl_xor_sync(0xffffffffu, v, o);
    return v;
}

__device__ __forceinline__ bool mask_at(const void* m, int mode, long i) {
    if (mode == 0) return ((const unsigned char*)m)[i] != 0;
    if (mode == 1) return ((const int*)m)[i] != 0;
    return ((const float*)m)[i] != 0.0f;
}

__device__ __forceinline__ void cp16(void* s, const void* g) {
    unsigned sa = (unsigned)__cvta_generic_to_shared(s);
    asm volatile("cp.async.cg.shared.global [%0], [%1], 16;\n" :: "r"(sa), "l"(g));
}
__device__ __forceinline__ void cp_commit() {
    asm volatile("cp.async.commit_group;\n");
}
template <int N>
__device__ __forceinline__ void cp_wait() {
    asm volatile("cp.async.wait_group %0;\n" :: "n"(N));
}

// ---------------- tensor-core primitives -------------------------------------
__device__ __forceinline__ void ldsm_x4(unsigned r[4], const void* p) {
    unsigned a = (unsigned)__cvta_generic_to_shared(p);
    asm volatile("ldmatrix.sync.aligned.m8n8.x4.shared.b16 {%0,%1,%2,%3}, [%4];"
                 : "=r"(r[0]), "=r"(r[1]), "=r"(r[2]), "=r"(r[3]) : "r"(a));
}
__device__ __forceinline__ void ldsm_x4t(unsigned r[4], const void* p) {
    unsigned a = (unsigned)__cvta_generic_to_shared(p);
    asm volatile("ldmatrix.sync.aligned.m8n8.x4.trans.shared.b16 {%0,%1,%2,%3}, [%4];"
                 : "=r"(r[0]), "=r"(r[1]), "=r"(r[2]), "=r"(r[3]) : "r"(a));
}
// f16 accumulate: c = 2 regs, each packed half2
__device__ __forceinline__ void mma_f16(unsigned c[2], const unsigned a[4], const unsigned* b) {
    asm volatile(
        "mma.sync.aligned.m16n8k16.row.col.f16.f16.f16.f16 "
        "{%0,%1},{%2,%3,%4,%5},{%6,%7},{%0,%1};"
        : "+r"(c[0]), "+r"(c[1])
        : "r"(a[0]), "r"(a[1]), "r"(a[2]), "r"(a[3]), "r"(b[0]), "r"(b[1]));
}

// ---------------- K0: merged mask-probe + weight convert ---------------------
__global__ void k_prep(const unsigned char* m, const float* __restrict__ wqkv,
                       const float* __restrict__ wproj) {
    int blk = blockIdx.x, tid = threadIdx.x;
    if (blk < 64) {
        __shared__ unsigned flags;
        if (tid == 0) flags = 0;
        __syncthreads();
        const unsigned int* w = (const unsigned int*)m;
        int base = blk * 512;
        unsigned f = 0;
        for (int i = tid; i < 512; i += blockDim.x) {
            unsigned x = w[base + i];
            if (x > 1u) f |= 1u;
            if (x != 0u && x != 0x3F800000u) f |= 2u;
        }
        if (f) atomicOr(&flags, f);
        __syncthreads();
        if (tid == 0) g_det[blk] = flags;
    } else {
        int i = (blk - 64) * 256 + tid;          // 0 .. 65535
        g_wv16[i] = __float2half(wqkv[131072 + i]);
        g_wp16[i] = __float2half(wproj[i]);
    }
}

__device__ __forceinline__ int mask_mode_from_partials() {
    unsigned f = 0;
#pragma unroll
    for (int i = 0; i < 64; i++) f |= g_det[i];
    return (!(f & 1u)) ? 1 : ((!(f & 2u)) ? 2 : 0);
}

// ---------------- K1: xbar (masked mean of LN) + xn0 -------------------------
__global__ void k_xbar(const float* __restrict__ x, const void* __restrict__ mask,
                       const float* __restrict__ lnw, const float* __restrict__ lnb) {
    int bv = blockIdx.x;
    int w = threadIdx.x >> 5, lane = threadIdx.x & 31;
    int mode = mask_mode_from_partials();

    float lw[8], lb[8], acc[8];
#pragma unroll
    for (int j = 0; j < 8; j++) {
        lw[j] = lnw[lane + 32 * j];
        lb[j] = lnb[lane + 32 * j];
        acc[j] = 0.0f;
    }
    float cnt = 0.0f;

    for (int t = w; t < T1_; t += 8) {
        const float* row = x + ((size_t)bv * T1_ + t) * D_;
        float r[8];
#pragma unroll
        for (int j = 0; j < 8; j++) r[j] = row[lane + 32 * j];
        float s = 0.0f;
#pragma unroll
        for (int j = 0; j < 8; j++) s += r[j];
        s = warp_sum(s);
        float mu = s * (1.0f / 256.0f);
        float v = 0.0f;
#pragma unroll
        for (int j = 0; j < 8; j++) { float d = r[j] - mu; v += d * d; }
        v = warp_sum(v);
        float rs = rsqrtf(v * (1.0f / 256.0f) + EPS);

        bool m = (t == 0) ? true : mask_at(mask, mode, (long)bv * T_ + (t - 1));
        if (m) {
#pragma unroll
            for (int j = 0; j < 8; j++)
                acc[j] += (r[j] - mu) * rs * lw[j] + lb[j];
            cnt += 1.0f;
        }
        if (t == 0) {
#pragma unroll
            for (int j = 0; j < 8; j++)
                g_xn0[bv * D_ + lane + 32 * j] =
                    __float2bfloat16((r[j] - mu) * rs * lw[j] + lb[j]);
        }
    }

    __shared__ float sAcc[8][256];
    __shared__ float sCnt[8];
#pragma unroll
    for (int j = 0; j < 8; j++) sAcc[w][lane + 32 * j] = acc[j];
    if (lane == 0) sCnt[w] = cnt;
    __syncthreads();

    int d = threadIdx.x;
    float tot = 0.0f, c = 0.0f;
#pragma unroll
    for (int i = 0; i < 8; i++) { tot += sAcc[i][d]; c += sCnt[i]; }
    c = fmaxf(c, 1.0f);
    g_xbar[bv * D_ + d] = __float2bfloat16(tot / c);
}

// ---------------- K2: fused q/k projection + softmax per (b,h) ---------------
// 64 blocks x 256 threads. q = xn0_b @ Wq_h^T, k = xbar_b @ Wk_h^T (fp32
// weights straight from gmem), then 64x64 softmax -> g_attn (f16).
__global__ void k_qkattn(const float* __restrict__ wqkv) {
    extern __shared__ char smem[];
    __nv_bfloat16* sX = (__nv_bfloat16*)(smem + QA_X);   // [64][264]
    __nv_bfloat16* sY = (__nv_bfloat16*)(smem + QA_Y);   // [64][264]
    float* qs = (float*)(smem + QA_Q);                   // [64][36]
    float* ks = (float*)(smem + QA_K);                   // [64][36]
    float* sc = (float*)(smem + QA_S);                   // [64][65]

    int b = blockIdx.x >> 3, h = blockIdx.x & 7;
    int tid = threadIdx.x;

    // load xn0/xbar tiles for this b
    for (int i = tid; i < 64 * 32; i += 256) {
        int r = i >> 5, c = i & 31;
        *(uint4*)(sX + r * 264 + c * 8) =
            *(const uint4*)(g_xn0 + (size_t)(b * 64 + r) * 256 + c * 8);
        *(uint4*)(sY + r * 264 + c * 8) =
            *(const uint4*)(g_xbar + (size_t)(b * 64 + r) * 256 + c * 8);
    }
    __syncthreads();

    // thread (v, d4): outputs d = d4*8 .. +8 for row v
    {
        int v = tid >> 2, d4 = tid & 3;
        const float* wq = wqkv + (size_t)(h * 32 + d4 * 8) * 256;
        // K projection = rows 256..511 of w_qkv, i.e. element offset 65536
        const float* wk = wqkv + 65536 + (size_t)(h * 32 + d4 * 8) * 256;
        float qa[8], ka[8];
#pragma unroll
        for (int j = 0; j < 8; j++) { qa[j] = 0.0f; ka[j] = 0.0f; }
        for (int c = 0; c < 256; c += 4) {
            float2 xv0 = __bfloat1622float2(*(const __nv_bfloat162*)(sX + v * 264 + c));
            float2 xv1 = __bfloat1622float2(*(const __nv_bfloat162*)(sX + v * 264 + c + 2));
            float2 yv0 = __bfloat1622float2(*(const __nv_bfloat162*)(sY + v * 264 + c));
            float2 yv1 = __bfloat1622float2(*(const __nv_bfloat162*)(sY + v * 264 + c + 2));
#pragma unroll
            for (int j = 0; j < 8; j++) {
                float4 wv = *(const float4*)(wq + (size_t)j * 256 + c);
                qa[j] += xv0.x * wv.x + xv0.y * wv.y + xv1.x * wv.z + xv1.y * wv.w;
                float4 kv = *(const float4*)(wk + (size_t)j * 256 + c);
                ka[j] += yv0.x * kv.x + yv0.y * kv.y + yv1.x * kv.z + yv1.y * kv.w;
            }
        }
#pragma unroll
        for (int j = 0; j < 8; j++) {
            qs[v * 36 + d4 * 8 + j] = qa[j];
            ks[v * 36 + d4 * 8 + j] = ka[j];
        }
    }
    __syncthreads();

    // scores
    const float scale = rsqrtf((float)DH_);
    for (int i = tid; i < 64 * 64; i += 256) {
        int vq = i >> 6, vk = i & 63;
        float s = 0.0f;
#pragma unroll
        for (int d = 0; d < 32; d++) s += qs[vq * 36 + d] * ks[vk * 36 + d];
        sc[vq * 65 + vk] = s * scale;
    }
    __syncthreads();

    if (tid < 64) {
        int vq = tid;
        float mx = -1e30f;
        for (int vk = 0; vk < 64; vk++) mx = fmaxf(mx, sc[vq * 65 + vk]);
        float sum = 0.0f;
        for (int vk = 0; vk < 64; vk++) {
            float e = expf(sc[vq * 65 + vk] - mx);
            sc[vq * 65 + vk] = e;
            sum += e;
        }
        float inv = 1.0f / sum;
        __half* dst = g_attn + (size_t)((b * H_ + h) * 64 + vq) * 64;
        for (int vk = 0; vk < 64; vk++) dst[vk] = __float2half(sc[vq * 65 + vk] * inv);
    }
}

// ---------------- k_main helpers ---------------------------------------------
// load one K=32 chunk: W[n=0..255][kc*32 .. +32) -> sW [256][LDW]
__device__ __forceinline__ void load_wchunk(__half* sW, const __half* __restrict__ Wg,
                                            int kc, int tid) {
#pragma unroll
    for (int i = 0; i < 2; i++) {
        int idx = tid + i * 512;            // 0..1023
        int n = idx >> 2, seg = idx & 3;
        cp16(sW + n * LDW + seg * 8, Wg + (size_t)n * 256 + kc * 32 + seg * 8);
    }
    cp_commit();
}

// C(128x256) = A(128x256 f16 in sA) @ W(256x256 f16)^T, f16 accumulate.
// 16 warps: rb = w>>2 (32 rows), cb = w&3 (64 cols). K=32 chunks, 2 buffers.
// Caller pre-issued chunk0 into sW0. Trailing sync protects sA for reuse.
__device__ __forceinline__ void gemm_k256(const __half* __restrict__ Wg,
                                          const __half* sA,
                                          __half* sW0, __half* sW1,
                                          unsigned acc[2][8][2], int tid, int lane) {
    int w = tid >> 5, rb = w >> 2, cb = w & 3;
#pragma unroll
    for (int i = 0; i < 2; i++)
#pragma unroll
        for (int j = 0; j < 8; j++) { acc[i][j][0] = 0u; acc[i][j][1] = 0u; }

    int arow = lane & 15, acolb = (lane >> 4) << 3;
    int brow = (lane & 7) + ((lane & 16) ? 8 : 0), bcolb = (lane & 8) ? 8 : 0;

#pragma unroll
    for (int kc = 0; kc < 8; kc++) {
        const __half* cur = (kc & 1) ? sW1 : sW0;
        __half* nxt = (kc & 1) ? sW0 : sW1;
        if (kc < 7) { load_wchunk(nxt, Wg, kc + 1, tid); cp_wait<1>(); }
        else        { cp_wait<0>(); }
        __syncthreads();
#pragma unroll
        for (int s = 0; s < 2; s++) {
            int k0 = s * 16;
            unsigned a0[4], a1[4];
            ldsm_x4(a0, sA + (rb * 32 + arow) * LDA + kc * 32 + k0 + acolb);
            ldsm_x4(a1, sA + (rb * 32 + 16 + arow) * LDA + kc * 32 + k0 + acolb);
#pragma unroll
            for (int jj = 0; jj < 4; jj++) {
                unsigned bb[4];
                ldsm_x4(bb, cur + (cb * 64 + jj * 16 + brow) * LDW + k0 + bcolb);
                mma_f16(acc[0][jj * 2 + 0], a0, bb + 0);
                mma_f16(acc[0][jj * 2 + 1], a0, bb + 2);
                mma_f16(acc[1][jj * 2 + 0], a1, bb + 0);
                mma_f16(acc[1][jj * 2 + 1], a1, bb + 2);
            }
        }
        __syncthreads();
    }
}

// store f16 accumulators (packed half2) straight into sA
__device__ __forceinline__ void store_acc_f16(unsigned acc[2][8][2], __half* sA,
                                              int tid, int lane) {
    int w = tid >> 5, rb = w >> 2, cb = w & 3;
    int r0 = rb * 32 + (lane >> 2), c0 = cb * 64 + (lane & 3) * 2;
#pragma unroll
    for (int i = 0; i < 2; i++)
#pragma unroll
        for (int jj = 0; jj < 8; jj++) {
            *(unsigned*)(sA + (r0 + i * 16) * LDA + c0 + jj * 8) = acc[i][jj][0];
            *(unsigned*)(sA + (r0 + i * 16 + 8) * LDA + c0 + jj * 8) = acc[i][jj][1];
        }
}

// ---------------- K3: fused LN + V-GEMM + attn-mix + proj + residual ---------
// One block per (b, t-pair): 128 rows (2 t) x 256 cols. 512 threads, f16 HMMA.
// 2 blocks per SM (smem 108.5 KB, 64-reg cap).
__global__ void __launch_bounds__(512, 2)
k_main(const float* __restrict__ x, const float* __restrict__ lnw,
       const float* __restrict__ lnb, const float* __restrict__ bproj,
       float* __restrict__ out) {
    extern __shared__ char smem[];
    __half* sA  = (__half*)smem;                        // [128][LDA]
    __half* sW0 = (__half*)(smem + OFF_W0);             // [256][LDW]
    __half* sW1 = (__half*)(smem + OFF_W1);             // [256][LDW]

    int b = blockIdx.x / 129, tp = blockIdx.x % 129;
    int t0 = tp * 2;
    bool dup = (t0 == 256);
    int t1 = dup ? t0 : t0 + 1;
    int tid = threadIdx.x, w = tid >> 5, lane = tid & 31;

    // Wv chunk0 prefetch (hidden under LN)
    load_wchunk(sW0, g_wv16, 0, tid);

    // ---- LayerNorm: 128 rows -> sA f16 ----
    for (int r = w; r < 128; r += 16) {
        int t = (r < 64) ? t0 : t1;
        int v = r & 63;
        const float* rowp = x + ((size_t)(b * 64 + v) * T1_ + t) * D_ + lane * 8;
        float4 p0 = *(const float4*)rowp;
        float4 p1 = *(const float4*)(rowp + 4);
        float rr[8] = {p0.x, p0.y, p0.z, p0.w, p1.x, p1.y, p1.z, p1.w};
        float s = 0.0f;
#pragma unroll
        for (int j = 0; j < 8; j++) s += rr[j];
        s = warp_sum(s);
        float mu = s * (1.0f / 256.0f);
        float var = 0.0f;
#pragma unroll
        for (int j = 0; j < 8; j++) { float d = rr[j] - mu; var += d * d; }
        var = warp_sum(var);
        float rs = rsqrtf(var * (1.0f / 256.0f) + EPS);
        float4 w0 = *(const float4*)(lnw + lane * 8);
        float4 w1 = *(const float4*)(lnw + lane * 8 + 4);
        float4 b0 = *(const float4*)(lnb + lane * 8);
        float4 b1 = *(const float4*)(lnb + lane * 8 + 4);
        float lwv[8] = {w0.x, w0.y, w0.z, w0.w, w1.x, w1.y, w1.z, w1.w};
        float lbv[8] = {b0.x, b0.y, b0.z, b0.w, b1.x, b1.y, b1.z, b1.w};
#pragma unroll
        for (int j = 0; j < 4; j++) {
            float2 fv = make_float2(
                (rr[2 * j] - mu) * rs * lwv[2 * j] + lbv[2 * j],
                (rr[2 * j + 1] - mu) * rs * lwv[2 * j + 1] + lbv[2 * j + 1]);
            *(__half2*)(sA + r * LDA + lane * 8 + 2 * j) = __float22half2_rn(fv);
        }
    }
    __syncthreads();

    // ---- GEMM1: vf = xn @ Wv^T (f16 acc) ----
    {
        unsigned acc[2][8][2];
        gemm_k256(g_wv16, sA, sW0, sW1, acc, tid, lane);
        load_wchunk(sW0, g_wp16, 0, tid);   // prefetch Wp chunk0 (sW0 free)
        store_acc_f16(acc, sA, tid, lane);  // vf into sA (already f16)
    }
    __syncthreads();

    // ---- attn mixing: warp (tsub = w>>3, h = w&7), f16 HMMA ----
    {
        int tsub = w >> 3, h = w & 7;
        unsigned mc[4][4][2];
#pragma unroll
        for (int a = 0; a < 4; a++)
#pragma unroll
            for (int c = 0; c < 4; c++) { mc[a][c][0] = 0u; mc[a][c][1] = 0u; }

        const __half* att = g_attn + (size_t)(b * H_ + h) * 64 * 64;
        int lr = lane >> 2, lc = (lane & 3) * 2;
        int trow = lane & 15, tcolb = (lane & 16) ? 8 : 0;
#pragma unroll
        for (int kt = 0; kt < 4; kt++) {
            int k0 = kt * 16;
            unsigned bb0[4], bb1[4];
            ldsm_x4t(bb0, sA + (tsub * 64 + k0 + trow) * LDA + h * 32 + tcolb);
            ldsm_x4t(bb1, sA + (tsub * 64 + k0 + trow) * LDA + h * 32 + 16 + tcolb);
#pragma unroll
            for (int rt = 0; rt < 4; rt++) {
                const __half* ap = att + (size_t)(rt * 16 + lr) * 64 + k0 + lc;
                unsigned aa[4];
                aa[0] = *(const unsigned*)ap;
                aa[1] = *(const unsigned*)(ap + 8 * 64);
                aa[2] = *(const unsigned*)(ap + 8);
                aa[3] = *(const unsigned*)(ap + 8 * 64 + 8);
                mma_f16(mc[rt][0], aa, bb0 + 0);
                mma_f16(mc[rt][1], aa, bb0 + 2);
                mma_f16(mc[rt][2], aa, bb1 + 0);
                mma_f16(mc[rt][3], aa, bb1 + 2);
            }
        }
        // per-warp tile [tsub*64 rows][h*32 cols] is self-contained
        int r0 = tsub * 64 + (lane >> 2), c0 = h * 32 + (lane & 3) * 2;
#pragma unroll
        for (int rt = 0; rt < 4; rt++)
#pragma unroll
            for (int jj = 0; jj < 4; jj++) {
                *(unsigned*)(sA + (r0 + rt * 16) * LDA + c0 + jj * 8) = mc[rt][jj][0];
                *(unsigned*)(sA + (r0 + rt * 16 + 8) * LDA + c0 + jj * 8) = mc[rt][jj][1];
            }
    }
    __syncthreads();

    // ---- GEMM2: proj = mixed @ Wp^T (f16 acc), epilogue from registers ----
    {
        unsigned acc[2][8][2];
        gemm_k256(g_wp16, sA, sW0, sW1, acc, tid, lane);

        int rb = w >> 2, cb = w & 3;
        if (!(dup && rb >= 2)) {
            int r0 = rb * 32 + (lane >> 2), c0 = cb * 64 + (lane & 3) * 2;
#pragma unroll
            for (int i = 0; i < 2; i++)
#pragma unroll
                for (int half = 0; half < 2; half++) {
                    int rr = r0 + i * 16 + half * 8;
                    int v = rr & 63;
                    int t = (rr < 64) ? t0 : t1;
                    size_t base = ((size_t)(b * 64 + v) * T1_ + t) * D_;
#pragma unroll
                    for (int jj = 0; jj < 8; jj++) {
                        int c = c0 + jj * 8;
                        size_t gi = base + c;
                        float2 xv = *(const float2*)(x + gi);
                        float2 pv = __half22float2(
                            *(const __half2*)&acc[i][jj][half]);
                        float2 o;
                        o.x = pv.x + bproj[c] + xv.x;
                        o.y = pv.y + bproj[c + 1] + xv.y;
                        *(float2*)(out + gi) = o;
                    }
                }
        }
    }
}

// ---------------- launch ----------------------------------------------------
extern "C" void kernel_launch(void* const* d_in, const int* in_sizes, int n_in,
                              void* d_out, int out_size) {
    const float* x     = (const float*)d_in[0];
    const void*  mask  = d_in[1];
    const float* lnw   = (const float*)d_in[2];
    const float* lnb   = (const float*)d_in[3];
    const float* wqkv  = (const float*)d_in[4];
    const float* wproj = (const float*)d_in[5];
    const float* bproj = (const float*)d_in[6];
    float* out = (float*)d_out;

    cudaFuncSetAttribute(k_main, cudaFuncAttributeMaxDynamicSharedMemorySize, SM_MAIN);
    cudaFuncSetAttribute(k_qkattn, cudaFuncAttributeMaxDynamicSharedMemorySize, SM_QA);

    k_prep<<<320, 256>>>((const unsigned char*)mask, wqkv, wproj);
    k_xbar<<<B_ * V_, 256>>>(x, mask, lnw, lnb);
    k_qkattn<<<64, 256, SM_QA>>>(wqkv);
    k_main<<<B_ * 129, 512, SM_MAIN>>>(x, lnw, lnb, bproj, out);
}

// round 16
// speedup vs baseline: 1.2434x; 1.2434x over previous
#include <cuda_runtime.h>
#include <cuda_bf16.h>
#include <cuda_fp16.h>
#include <mma.h>

using namespace nvcuda;

namespace {
constexpr int B_ = 8, V_ = 64, T_ = 256, T1_ = 257, D_ = 256, H_ = 8, DH_ = 32;
constexpr float EPS = 1e-5f;
constexpr int LDA = 264;                 // f16 elems per sA row (528B)
constexpr int LDW = 40;                  // f16 elems per K=32 weight-chunk row (80B)
// k_main dynamic smem layout (bytes)
constexpr int OFF_W0 = 128 * LDA * 2;                // sA = 67584
constexpr int OFF_W1 = OFF_W0 + 256 * LDW * 2;       // +20480
constexpr int SM_MAIN = OFF_W1 + 256 * LDW * 2;      // 108544 -> 2 blocks/SM
constexpr int SM_QK = 2 * 64 * LDA * 2;              // 67584
}

// ---------------- scratch (device globals) ----------------------------------
__device__ __nv_bfloat16 g_wb[512 * 256];      // bf16 Wq,Wk
__device__ __half g_wv16[256 * 256];           // f16 Wv
__device__ __half g_wp16[256 * 256];           // f16 Wp
__device__ __nv_bfloat16 g_xn0[512 * 256];     // LN(x[:,:,0])
__device__ __nv_bfloat16 g_xbar[512 * 256];    // masked mean of LN(x)
__device__ float g_q[512 * 256];
__device__ float g_k[512 * 256];
__device__ __half g_attn[8 * 8 * 64 * 64];
__device__ unsigned g_det[64];                 // mask-probe partials

__device__ __forceinline__ float warp_sum(float v) {
#pragma unroll
    for (int o = 16; o; o >>= 1) v += __shfl_xor_sync(0xffffffffu, v, o);
    return v;
}

__device__ __forceinline__ bool mask_at(const void* m, int mode, long i) {
    if (mode == 0) return ((const unsigned char*)m)[i] != 0;
    if (mode == 1) return ((const int*)m)[i] != 0;
    return ((const float*)m)[i] != 0.0f;
}

__device__ __forceinline__ void cp16(void* s, const void* g) {
    unsigned sa = (unsigned)__cvta_generic_to_shared(s);
    asm volatile("cp.async.cg.shared.global [%0], [%1], 16;\n" :: "r"(sa), "l"(g));
}
__device__ __forceinline__ void cp_commit() {
    asm volatile("cp.async.commit_group;\n");
}
template <int N>
__device__ __forceinline__ void cp_wait() {
    asm volatile("cp.async.wait_group %0;\n" :: "n"(N));
}

// ---------------- tensor-core primitives -------------------------------------
__device__ __forceinline__ void ldsm_x4(unsigned r[4], const void* p) {
    unsigned a = (unsigned)__cvta_generic_to_shared(p);
    asm volatile("ldmatrix.sync.aligned.m8n8.x4.shared.b16 {%0,%1,%2,%3}, [%4];"
                 : "=r"(r[0]), "=r"(r[1]), "=r"(r[2]), "=r"(r[3]) : "r"(a));
}
__device__ __forceinline__ void ldsm_x4t(unsigned r[4], const void* p) {
    unsigned a = (unsigned)__cvta_generic_to_shared(p);
    asm volatile("ldmatrix.sync.aligned.m8n8.x4.trans.shared.b16 {%0,%1,%2,%3}, [%4];"
                 : "=r"(r[0]), "=r"(r[1]), "=r"(r[2]), "=r"(r[3]) : "r"(a));
}
// f16 accumulate: c = 2 regs, each packed half2
__device__ __forceinline__ void mma_f16(unsigned c[2], const unsigned a[4], const unsigned* b) {
    asm volatile(
        "mma.sync.aligned.m16n8k16.row.col.f16.f16.f16.f16 "
        "{%0,%1},{%2,%3,%4,%5},{%6,%7},{%0,%1};"
        : "+r"(c[0]), "+r"(c[1])
        : "r"(a[0]), "r"(a[1]), "r"(a[2]), "r"(a[3]), "r"(b[0]), "r"(b[1]));
}

// ---------------- K0: merged mask-probe + weight converts --------------------
// blocks 0..63: probe 512 uints each of the mask buffer.
// blocks 64..575: convert Wq/Wk to bf16 (g_wb, 131072 elems); blocks 64..319
// additionally convert Wv and Wp to f16.
__global__ void k_prep(const unsigned char* m, const float* __restrict__ wqkv,
                       const float* __restrict__ wproj) {
    int blk = blockIdx.x, tid = threadIdx.x;
    if (blk < 64) {
        __shared__ unsigned flags;
        if (tid == 0) flags = 0;
        __syncthreads();
        const unsigned int* w = (const unsigned int*)m;
        int base = blk * 512;
        unsigned f = 0;
        for (int i = tid; i < 512; i += blockDim.x) {
            unsigned x = w[base + i];
            if (x > 1u) f |= 1u;
            if (x != 0u && x != 0x3F800000u) f |= 2u;
        }
        if (f) atomicOr(&flags, f);
        __syncthreads();
        if (tid == 0) g_det[blk] = flags;
    } else {
        int i = (blk - 64) * 256 + tid;          // 0 .. 131071
        g_wb[i] = __float2bfloat16(wqkv[i]);
        if (i < 65536) {
            g_wv16[i] = __float2half(wqkv[131072 + i]);
            g_wp16[i] = __float2half(wproj[i]);
        }
    }
}

__device__ __forceinline__ int mask_mode_from_partials() {
    unsigned f = 0;
#pragma unroll
    for (int i = 0; i < 64; i++) f |= g_det[i];
    return (!(f & 1u)) ? 1 : ((!(f & 2u)) ? 2 : 0);
}

// ---------------- K1: xbar (masked mean of LN) + xn0 -------------------------
__global__ void k_xbar(const float* __restrict__ x, const void* __restrict__ mask,
                       const float* __restrict__ lnw, const float* __restrict__ lnb) {
    int bv = blockIdx.x;
    int w = threadIdx.x >> 5, lane = threadIdx.x & 31;
    int mode = mask_mode_from_partials();

    float lw[8], lb[8], acc[8];
#pragma unroll
    for (int j = 0; j < 8; j++) {
        lw[j] = lnw[lane + 32 * j];
        lb[j] = lnb[lane + 32 * j];
        acc[j] = 0.0f;
    }
    float cnt = 0.0f;

    for (int t = w; t < T1_; t += 8) {
        const float* row = x + ((size_t)bv * T1_ + t) * D_;
        float r[8];
#pragma unroll
        for (int j = 0; j < 8; j++) r[j] = row[lane + 32 * j];
        float s = 0.0f;
#pragma unroll
        for (int j = 0; j < 8; j++) s += r[j];
        s = warp_sum(s);
        float mu = s * (1.0f / 256.0f);
        float v = 0.0f;
#pragma unroll
        for (int j = 0; j < 8; j++) { float d = r[j] - mu; v += d * d; }
        v = warp_sum(v);
        float rs = rsqrtf(v * (1.0f / 256.0f) + EPS);

        bool m = (t == 0) ? true : mask_at(mask, mode, (long)bv * T_ + (t - 1));
        if (m) {
#pragma unroll
            for (int j = 0; j < 8; j++)
                acc[j] += (r[j] - mu) * rs * lw[j] + lb[j];
            cnt += 1.0f;
        }
        if (t == 0) {
#pragma unroll
            for (int j = 0; j < 8; j++)
                g_xn0[bv * D_ + lane + 32 * j] =
                    __float2bfloat16((r[j] - mu) * rs * lw[j] + lb[j]);
        }
    }

    __shared__ float sAcc[8][256];
    __shared__ float sCnt[8];
#pragma unroll
    for (int j = 0; j < 8; j++) sAcc[w][lane + 32 * j] = acc[j];
    if (lane == 0) sCnt[w] = cnt;
    __syncthreads();

    int d = threadIdx.x;
    float tot = 0.0f, c = 0.0f;
#pragma unroll
    for (int i = 0; i < 8; i++) { tot += sAcc[i][d]; c += sCnt[i]; }
    c = fmaxf(c, 1.0f);
    g_xbar[bv * D_ + d] = __float2bfloat16(tot / c);
}

// ---------------- K2: q = xn0 @ Wq^T, k = xbar @ Wk^T (wmma) -----------------
__global__ void k_qk() {
    extern __shared__ char smem[];
    __nv_bfloat16* sA = (__nv_bfloat16*)smem;
    __nv_bfloat16* sB = sA + 64 * LDA;

    int bid = blockIdx.x;
    int mat = bid >> 5, tile = bid & 31;
    int tr = tile >> 2, tc = tile & 3;
    const __nv_bfloat16* Ag = mat == 0 ? g_xn0 : g_xbar;
    const __nv_bfloat16* Wg = g_wb + (size_t)mat * 256 * 256;
    float* Cg = mat == 0 ? g_q : g_k;

    int tid = threadIdx.x;
    for (int idx = tid; idx < 64 * 32; idx += 256) {
        int r = idx >> 5, c = idx & 31;
        *(uint4*)(sA + r * LDA + c * 8) = *(const uint4*)(Ag + (size_t)(tr * 64 + r) * 256 + c * 8);
        *(uint4*)(sB + r * LDA + c * 8) = *(const uint4*)(Wg + (size_t)(tc * 64 + r) * 256 + c * 8);
    }
    __syncthreads();

    int w = tid >> 5, rt = w & 3, cg = w >> 2;
    wmma::fragment<wmma::accumulator, 16, 16, 16, float> acc[2];
    wmma::fill_fragment(acc[0], 0.0f);
    wmma::fill_fragment(acc[1], 0.0f);
#pragma unroll
    for (int k = 0; k < 16; k++) {
        wmma::fragment<wmma::matrix_a, 16, 16, 16, __nv_bfloat16, wmma::row_major> af;
        wmma::load_matrix_sync(af, sA + (rt * 16) * LDA + k * 16, LDA);
#pragma unroll
        for (int j = 0; j < 2; j++) {
            wmma::fragment<wmma::matrix_b, 16, 16, 16, __nv_bfloat16, wmma::col_major> bf;
            wmma::load_matrix_sync(bf, sB + (cg * 32 + j * 16) * LDA + k * 16, LDA);
            wmma::mma_sync(acc[j], af, bf, acc[j]);
        }
    }
#pragma unroll
    for (int j = 0; j < 2; j++)
        wmma::store_matrix_sync(
            Cg + (size_t)(tr * 64 + rt * 16) * 256 + tc * 64 + cg * 32 + j * 16,
            acc[j], 256, wmma::mem_row_major);
}

// ---------------- K3: attention softmax (per b,h: 64x64) --------------------
__global__ void k_attn() {
    int b = blockIdx.x / H_, h = blockIdx.x % H_;
    __shared__ float qh[64][32], kh[64][32], sc[64][64];
    int tid = threadIdx.x;

    for (int i = tid; i < 64 * 32; i += 128) {
        int vq = i >> 5, d = i & 31;
        qh[vq][d] = g_q[(size_t)(b * 64 + vq) * D_ + h * 32 + d];
        kh[vq][d] = g_k[(size_t)(b * 64 + vq) * D_ + h * 32 + d];
    }
    __syncthreads();

    const float scale = rsqrtf((float)DH_);
    for (int i = tid; i < 64 * 64; i += 128) {
        int vq = i >> 6, vk = i & 63;
        float s = 0.0f;
#pragma unroll
        for (int d = 0; d < 32; d++) s += qh[vq][d] * kh[vk][d];
        sc[vq][vk] = s * scale;
    }
    __syncthreads();

    if (tid < 64) {
        int vq = tid;
        float mx = -1e30f;
        for (int vk = 0; vk < 64; vk++) mx = fmaxf(mx, sc[vq][vk]);
        float sum = 0.0f;
        for (int vk = 0; vk < 64; vk++) { float e = expf(sc[vq][vk] - mx); sc[vq][vk] = e; sum += e; }
        float inv = 1.0f / sum;
        __half* dst = g_attn + (size_t)((b * H_ + h) * 64 + vq) * 64;
        for (int vk = 0; vk < 64; vk++) dst[vk] = __float2half(sc[vq][vk] * inv);
    }
}

// ---------------- k_main helpers ---------------------------------------------
// load one K=32 chunk: W[n=0..255][kc*32 .. +32) -> sW [256][LDW]
__device__ __forceinline__ void load_wchunk(__half* sW, const __half* __restrict__ Wg,
                                            int kc, int tid) {
#pragma unroll
    for (int i = 0; i < 2; i++) {
        int idx = tid + i * 512;            // 0..1023
        int n = idx >> 2, seg = idx & 3;
        cp16(sW + n * LDW + seg * 8, Wg + (size_t)n * 256 + kc * 32 + seg * 8);
    }
    cp_commit();
}

// C(128x256) = A(128x256 f16 in sA) @ W(256x256 f16)^T, f16 accumulate.
// 16 warps: rb = w>>2 (32 rows), cb = w&3 (64 cols). K=32 chunks, 2 buffers.
__device__ __forceinline__ void gemm_k256(const __half* __restrict__ Wg,
                                          const __half* sA,
                                          __half* sW0, __half* sW1,
                                          unsigned acc[2][8][2], int tid, int lane) {
    int w = tid >> 5, rb = w >> 2, cb = w & 3;
#pragma unroll
    for (int i = 0; i < 2; i++)
#pragma unroll
        for (int j = 0; j < 8; j++) { acc[i][j][0] = 0u; acc[i][j][1] = 0u; }

    int arow = lane & 15, acolb = (lane >> 4) << 3;
    int brow = (lane & 7) + ((lane & 16) ? 8 : 0), bcolb = (lane & 8) ? 8 : 0;

#pragma unroll
    for (int kc = 0; kc < 8; kc++) {
        const __half* cur = (kc & 1) ? sW1 : sW0;
        __half* nxt = (kc & 1) ? sW0 : sW1;
        if (kc < 7) { load_wchunk(nxt, Wg, kc + 1, tid); cp_wait<1>(); }
        else        { cp_wait<0>(); }
        __syncthreads();
#pragma unroll
        for (int s = 0; s < 2; s++) {
            int k0 = s * 16;
            unsigned a0[4], a1[4];
            ldsm_x4(a0, sA + (rb * 32 + arow) * LDA + kc * 32 + k0 + acolb);
            ldsm_x4(a1, sA + (rb * 32 + 16 + arow) * LDA + kc * 32 + k0 + acolb);
#pragma unroll
            for (int jj = 0; jj < 4; jj++) {
                unsigned bb[4];
                ldsm_x4(bb, cur + (cb * 64 + jj * 16 + brow) * LDW + k0 + bcolb);
                mma_f16(acc[0][jj * 2 + 0], a0, bb + 0);
                mma_f16(acc[0][jj * 2 + 1], a0, bb + 2);
                mma_f16(acc[1][jj * 2 + 0], a1, bb + 0);
                mma_f16(acc[1][jj * 2 + 1], a1, bb + 2);
            }
        }
        __syncthreads();
    }
}

// store f16 accumulators (packed half2) straight into sA
__device__ __forceinline__ void store_acc_f16(unsigned acc[2][8][2], __half* sA,
                                              int tid, int lane) {
    int w = tid >> 5, rb = w >> 2, cb = w & 3;
    int r0 = rb * 32 + (lane >> 2), c0 = cb * 64 + (lane & 3) * 2;
#pragma unroll
    for (int i = 0; i < 2; i++)
#pragma unroll
        for (int jj = 0; jj < 8; jj++) {
            *(unsigned*)(sA + (r0 + i * 16) * LDA + c0 + jj * 8) = acc[i][jj][0];
            *(unsigned*)(sA + (r0 + i * 16 + 8) * LDA + c0 + jj * 8) = acc[i][jj][1];
        }
}

// ---------------- K4: fused LN + V-GEMM + attn-mix + proj + residual ---------
// One block per (b, t-pair): 128 rows (2 t) x 256 cols. 512 threads, f16 HMMA.
// 2 blocks per SM (smem 108.5 KB, 64-reg cap).
__global__ void __launch_bounds__(512, 2)
k_main(const float* __restrict__ x, const float* __restrict__ lnw,
       const float* __restrict__ lnb, const float* __restrict__ bproj,
       float* __restrict__ out) {
    extern __shared__ char smem[];
    __half* sA  = (__half*)smem;                        // [128][LDA]
    __half* sW0 = (__half*)(smem + OFF_W0);             // [256][LDW]
    __half* sW1 = (__half*)(smem + OFF_W1);             // [256][LDW]

    int b = blockIdx.x / 129, tp = blockIdx.x % 129;
    int t0 = tp * 2;
    bool dup = (t0 == 256);
    int t1 = dup ? t0 : t0 + 1;
    int tid = threadIdx.x, w = tid >> 5, lane = tid & 31;

    // Wv chunk0 prefetch (hidden under LN)
    load_wchunk(sW0, g_wv16, 0, tid);

    // ---- LayerNorm: 128 rows -> sA f16 ----
    for (int r = w; r < 128; r += 16) {
        int t = (r < 64) ? t0 : t1;
        int v = r & 63;
        const float* rowp = x + ((size_t)(b * 64 + v) * T1_ + t) * D_ + lane * 8;
        float4 p0 = *(const float4*)rowp;
        float4 p1 = *(const float4*)(rowp + 4);
        float rr[8] = {p0.x, p0.y, p0.z, p0.w, p1.x, p1.y, p1.z, p1.w};
        float s = 0.0f;
#pragma unroll
        for (int j = 0; j < 8; j++) s += rr[j];
        s = warp_sum(s);
        float mu = s * (1.0f / 256.0f);
        float var = 0.0f;
#pragma unroll
        for (int j = 0; j < 8; j++) { float d = rr[j] - mu; var += d * d; }
        var = warp_sum(var);
        float rs = rsqrtf(var * (1.0f / 256.0f) + EPS);
        float4 w0 = *(const float4*)(lnw + lane * 8);
        float4 w1 = *(const float4*)(lnw + lane * 8 + 4);
        float4 b0 = *(const float4*)(lnb + lane * 8);
        float4 b1 = *(const float4*)(lnb + lane * 8 + 4);
        float lwv[8] = {w0.x, w0.y, w0.z, w0.w, w1.x, w1.y, w1.z, w1.w};
        float lbv[8] = {b0.x, b0.y, b0.z, b0.w, b1.x, b1.y, b1.z, b1.w};
#pragma unroll
        for (int j = 0; j < 4; j++) {
            float2 fv = make_float2(
                (rr[2 * j] - mu) * rs * lwv[2 * j] + lbv[2 * j],
                (rr[2 * j + 1] - mu) * rs * lwv[2 * j + 1] + lbv[2 * j + 1]);
            *(__half2*)(sA + r * LDA + lane * 8 + 2 * j) = __float22half2_rn(fv);
        }
    }
    __syncthreads();

    // ---- GEMM1: vf = xn @ Wv^T (f16 acc) ----
    {
        unsigned acc[2][8][2];
        gemm_k256(g_wv16, sA, sW0, sW1, acc, tid, lane);
        load_wchunk(sW0, g_wp16, 0, tid);   // prefetch Wp chunk0 (sW0 free)
        store_acc_f16(acc, sA, tid, lane);  // vf into sA (already f16)
    }
    __syncthreads();

    // ---- attn mixing: warp (tsub = w>>3, h = w&7), f16 HMMA ----
    {
        int tsub = w >> 3, h = w & 7;
        unsigned mc[4][4][2];
#pragma unroll
        for (int a = 0; a < 4; a++)
#pragma unroll
            for (int c = 0; c < 4; c++) { mc[a][c][0] = 0u; mc[a][c][1] = 0u; }

        const __half* att = g_attn + (size_t)(b * H_ + h) * 64 * 64;
        int lr = lane >> 2, lc = (lane & 3) * 2;
        int trow = lane & 15, tcolb = (lane & 16) ? 8 : 0;
#pragma unroll
        for (int kt = 0; kt < 4; kt++) {
            int k0 = kt * 16;
            unsigned bb0[4], bb1[4];
            ldsm_x4t(bb0, sA + (tsub * 64 + k0 + trow) * LDA + h * 32 + tcolb);
            ldsm_x4t(bb1, sA + (tsub * 64 + k0 + trow) * LDA + h * 32 + 16 + tcolb);
#pragma unroll
            for (int rt = 0; rt < 4; rt++) {
                const __half* ap = att + (size_t)(rt * 16 + lr) * 64 + k0 + lc;
                unsigned aa[4];
                aa[0] = *(const unsigned*)ap;
                aa[1] = *(const unsigned*)(ap + 8 * 64);
                aa[2] = *(const unsigned*)(ap + 8);
                aa[3] = *(const unsigned*)(ap + 8 * 64 + 8);
                mma_f16(mc[rt][0], aa, bb0 + 0);
                mma_f16(mc[rt][1], aa, bb0 + 2);
                mma_f16(mc[rt][2], aa, bb1 + 0);
                mma_f16(mc[rt][3], aa, bb1 + 2);
            }
        }
        // per-warp tile [tsub*64 rows][h*32 cols] is self-contained
        int r0 = tsub * 64 + (lane >> 2), c0 = h * 32 + (lane & 3) * 2;
#pragma unroll
        for (int rt = 0; rt < 4; rt++)
#pragma unroll
            for (int jj = 0; jj < 4; jj++) {
                *(unsigned*)(sA + (r0 + rt * 16) * LDA + c0 + jj * 8) = mc[rt][jj][0];
                *(unsigned*)(sA + (r0 + rt * 16 + 8) * LDA + c0 + jj * 8) = mc[rt][jj][1];
            }
    }
    __syncthreads();

    // ---- GEMM2: proj = mixed @ Wp^T (f16 acc), epilogue from registers ----
    {
        unsigned acc[2][8][2];
        gemm_k256(g_wp16, sA, sW0, sW1, acc, tid, lane);

        int rb = w >> 2, cb = w & 3;
        if (!(dup && rb >= 2)) {
            int r0 = rb * 32 + (lane >> 2), c0 = cb * 64 + (lane & 3) * 2;
#pragma unroll
            for (int i = 0; i < 2; i++)
#pragma unroll
                for (int half = 0; half < 2; half++) {
                    int rr = r0 + i * 16 + half * 8;
                    int v = rr & 63;
                    int t = (rr < 64) ? t0 : t1;
                    size_t base = ((size_t)(b * 64 + v) * T1_ + t) * D_;
#pragma unroll
                    for (int jj = 0; jj < 8; jj++) {
                        int c = c0 + jj * 8;
                        size_t gi = base + c;
                        float2 xv = *(const float2*)(x + gi);
                        float2 pv = __half22float2(
                            *(const __half2*)&acc[i][jj][half]);
                        float2 o;
                        o.x = pv.x + bproj[c] + xv.x;
                        o.y = pv.y + bproj[c + 1] + xv.y;
                        *(float2*)(out + gi) = o;
                    }
                }
        }
    }
}

// ---------------- launch ----------------------------------------------------
extern "C" void kernel_launch(void* const* d_in, const int* in_sizes, int n_in,
                              void* d_out, int out_size) {
    const float* x     = (const float*)d_in[0];
    const void*  mask  = d_in[1];
    const float* lnw   = (const float*)d_in[2];
    const float* lnb   = (const float*)d_in[3];
    const float* wqkv  = (const float*)d_in[4];
    const float* wproj = (const float*)d_in[5];
    const float* bproj = (const float*)d_in[6];
    float* out = (float*)d_out;

    cudaFuncSetAttribute(k_main, cudaFuncAttributeMaxDynamicSharedMemorySize, SM_MAIN);
    cudaFuncSetAttribute(k_qk, cudaFuncAttributeMaxDynamicSharedMemorySize, SM_QK);

    k_prep<<<576, 256>>>((const unsigned char*)mask, wqkv, wproj);
    k_xbar<<<B_ * V_, 256>>>(x, mask, lnw, lnb);
    k_qk<<<64, 256, SM_QK>>>();
    k_attn<<<B_ * H_, 128>>>();
    k_main<<<B_ * 129, 512, SM_MAIN>>>(x, lnw, lnb, bproj, out);
}

// round 17
// speedup vs baseline: 1.2998x; 1.0454x over previous
#include <cuda_runtime.h>
#include <cuda_bf16.h>
#include <cuda_fp16.h>
#include <mma.h>

using namespace nvcuda;

namespace {
constexpr int B_ = 8, V_ = 64, T_ = 256, T1_ = 257, D_ = 256, H_ = 8, DH_ = 32;
constexpr float EPS = 1e-5f;
constexpr int LDA = 264;                 // f16 elems per sA row (528B)
constexpr int LDW = 40;                  // f16 elems per K=32 weight-chunk row (80B)
// k_main dynamic smem layout (bytes)
constexpr int OFF_W0 = 128 * LDA * 2;                // sA = 67584
constexpr int OFF_W1 = OFF_W0 + 256 * LDW * 2;       // +20480
constexpr int SM_MAIN = OFF_W1 + 256 * LDW * 2;      // 108544 -> 2 blocks/SM
constexpr int SM_QK = 2 * 64 * LDA * 2;              // 67584
}

// ---------------- scratch (device globals) ----------------------------------
__device__ __nv_bfloat16 g_wb[512 * 256];      // bf16 Wq,Wk
__device__ __half g_wv16[256 * 256];           // f16 Wv
__device__ __half g_wp16[256 * 256];           // f16 Wp
__device__ __nv_bfloat16 g_xn0[512 * 256];     // LN(x[:,:,0])
__device__ __nv_bfloat16 g_xbar[512 * 256];    // masked mean of LN(x)
__device__ float g_q[512 * 256];
__device__ float g_k[512 * 256];
__device__ __half g_attn[8 * 8 * 64 * 64];
__device__ unsigned g_det[64];                 // mask-probe partials

__device__ __forceinline__ float warp_sum(float v) {
#pragma unroll
    for (int o = 16; o; o >>= 1) v += __shfl_xor_sync(0xffffffffu, v, o);
    return v;
}

__device__ __forceinline__ bool mask_at(const void* m, int mode, long i) {
    if (mode == 0) return ((const unsigned char*)m)[i] != 0;
    if (mode == 1) return ((const int*)m)[i] != 0;
    return ((const float*)m)[i] != 0.0f;
}

__device__ __forceinline__ void cp16(void* s, const void* g) {
    unsigned sa = (unsigned)__cvta_generic_to_shared(s);
    asm volatile("cp.async.cg.shared.global [%0], [%1], 16;\n" :: "r"(sa), "l"(g));
}
__device__ __forceinline__ void cp_commit() {
    asm volatile("cp.async.commit_group;\n");
}
template <int N>
__device__ __forceinline__ void cp_wait() {
    asm volatile("cp.async.wait_group %0;\n" :: "n"(N));
}

// ---------------- tensor-core primitives -------------------------------------
__device__ __forceinline__ void ldsm_x4(unsigned r[4], const void* p) {
    unsigned a = (unsigned)__cvta_generic_to_shared(p);
    asm volatile("ldmatrix.sync.aligned.m8n8.x4.shared.b16 {%0,%1,%2,%3}, [%4];"
                 : "=r"(r[0]), "=r"(r[1]), "=r"(r[2]), "=r"(r[3]) : "r"(a));
}
__device__ __forceinline__ void ldsm_x4t(unsigned r[4], const void* p) {
    unsigned a = (unsigned)__cvta_generic_to_shared(p);
    asm volatile("ldmatrix.sync.aligned.m8n8.x4.trans.shared.b16 {%0,%1,%2,%3}, [%4];"
                 : "=r"(r[0]), "=r"(r[1]), "=r"(r[2]), "=r"(r[3]) : "r"(a));
}
// f16 accumulate: c = 2 regs, each packed half2
__device__ __forceinline__ void mma_f16(unsigned c[2], const unsigned a[4], const unsigned* b) {
    asm volatile(
        "mma.sync.aligned.m16n8k16.row.col.f16.f16.f16.f16 "
        "{%0,%1},{%2,%3,%4,%5},{%6,%7},{%0,%1};"
        : "+r"(c[0]), "+r"(c[1])
        : "r"(a[0]), "r"(a[1]), "r"(a[2]), "r"(a[3]), "r"(b[0]), "r"(b[1]));
}

// ---------------- K0: merged mask-probe + weight converts --------------------
__global__ void k_prep(const unsigned char* m, const float* __restrict__ wqkv,
                       const float* __restrict__ wproj) {
    int blk = blockIdx.x, tid = threadIdx.x;
    if (blk < 64) {
        __shared__ unsigned flags;
        if (tid == 0) flags = 0;
        __syncthreads();
        const unsigned int* w = (const unsigned int*)m;
        int base = blk * 512;
        unsigned f = 0;
        for (int i = tid; i < 512; i += blockDim.x) {
            unsigned x = w[base + i];
            if (x > 1u) f |= 1u;
            if (x != 0u && x != 0x3F800000u) f |= 2u;
        }
        if (f) atomicOr(&flags, f);
        __syncthreads();
        if (tid == 0) g_det[blk] = flags;
    } else {
        int i = (blk - 64) * 256 + tid;          // 0 .. 131071
        g_wb[i] = __float2bfloat16(wqkv[i]);
        if (i < 65536) {
            g_wv16[i] = __float2half(wqkv[131072 + i]);
            g_wp16[i] = __float2half(wproj[i]);
        }
    }
}

__device__ __forceinline__ int mask_mode_from_partials() {
    unsigned f = 0;
#pragma unroll
    for (int i = 0; i < 64; i++) f |= g_det[i];
    return (!(f & 1u)) ? 1 : ((!(f & 2u)) ? 2 : 0);
}

// ---------------- K1: xbar (masked mean of LN) + xn0 -------------------------
__global__ void k_xbar(const float* __restrict__ x, const void* __restrict__ mask,
                       const float* __restrict__ lnw, const float* __restrict__ lnb) {
    int bv = blockIdx.x;
    int w = threadIdx.x >> 5, lane = threadIdx.x & 31;
    int mode = mask_mode_from_partials();

    float lw[8], lb[8], acc[8];
#pragma unroll
    for (int j = 0; j < 8; j++) {
        lw[j] = lnw[lane + 32 * j];
        lb[j] = lnb[lane + 32 * j];
        acc[j] = 0.0f;
    }
    float cnt = 0.0f;

    for (int t = w; t < T1_; t += 8) {
        const float* row = x + ((size_t)bv * T1_ + t) * D_;
        float r[8];
#pragma unroll
        for (int j = 0; j < 8; j++) r[j] = row[lane + 32 * j];
        float s = 0.0f;
#pragma unroll
        for (int j = 0; j < 8; j++) s += r[j];
        s = warp_sum(s);
        float mu = s * (1.0f / 256.0f);
        float v = 0.0f;
#pragma unroll
        for (int j = 0; j < 8; j++) { float d = r[j] - mu; v += d * d; }
        v = warp_sum(v);
        float rs = rsqrtf(v * (1.0f / 256.0f) + EPS);

        bool m = (t == 0) ? true : mask_at(mask, mode, (long)bv * T_ + (t - 1));
        if (m) {
#pragma unroll
            for (int j = 0; j < 8; j++)
                acc[j] += (r[j] - mu) * rs * lw[j] + lb[j];
            cnt += 1.0f;
        }
        if (t == 0) {
#pragma unroll
            for (int j = 0; j < 8; j++)
                g_xn0[bv * D_ + lane + 32 * j] =
                    __float2bfloat16((r[j] - mu) * rs * lw[j] + lb[j]);
        }
    }

    __shared__ float sAcc[8][256];
    __shared__ float sCnt[8];
#pragma unroll
    for (int j = 0; j < 8; j++) sAcc[w][lane + 32 * j] = acc[j];
    if (lane == 0) sCnt[w] = cnt;
    __syncthreads();

    int d = threadIdx.x;
    float tot = 0.0f, c = 0.0f;
#pragma unroll
    for (int i = 0; i < 8; i++) { tot += sAcc[i][d]; c += sCnt[i]; }
    c = fmaxf(c, 1.0f);
    g_xbar[bv * D_ + d] = __float2bfloat16(tot / c);
}

// ---------------- K2: q = xn0 @ Wq^T, k = xbar @ Wk^T (wmma) -----------------
__global__ void k_qk() {
    extern __shared__ char smem[];
    __nv_bfloat16* sA = (__nv_bfloat16*)smem;
    __nv_bfloat16* sB = sA + 64 * LDA;

    int bid = blockIdx.x;
    int mat = bid >> 5, tile = bid & 31;
    int tr = tile >> 2, tc = tile & 3;
    const __nv_bfloat16* Ag = mat == 0 ? g_xn0 : g_xbar;
    const __nv_bfloat16* Wg = g_wb + (size_t)mat * 256 * 256;
    float* Cg = mat == 0 ? g_q : g_k;

    int tid = threadIdx.x;
    for (int idx = tid; idx < 64 * 32; idx += 256) {
        int r = idx >> 5, c = idx & 31;
        *(uint4*)(sA + r * LDA + c * 8) = *(const uint4*)(Ag + (size_t)(tr * 64 + r) * 256 + c * 8);
        *(uint4*)(sB + r * LDA + c * 8) = *(const uint4*)(Wg + (size_t)(tc * 64 + r) * 256 + c * 8);
    }
    __syncthreads();

    int w = tid >> 5, rt = w & 3, cg = w >> 2;
    wmma::fragment<wmma::accumulator, 16, 16, 16, float> acc[2];
    wmma::fill_fragment(acc[0], 0.0f);
    wmma::fill_fragment(acc[1], 0.0f);
#pragma unroll
    for (int k = 0; k < 16; k++) {
        wmma::fragment<wmma::matrix_a, 16, 16, 16, __nv_bfloat16, wmma::row_major> af;
        wmma::load_matrix_sync(af, sA + (rt * 16) * LDA + k * 16, LDA);
#pragma unroll
        for (int j = 0; j < 2; j++) {
            wmma::fragment<wmma::matrix_b, 16, 16, 16, __nv_bfloat16, wmma::col_major> bf;
            wmma::load_matrix_sync(bf, sB + (cg * 32 + j * 16) * LDA + k * 16, LDA);
            wmma::mma_sync(acc[j], af, bf, acc[j]);
        }
    }
#pragma unroll
    for (int j = 0; j < 2; j++)
        wmma::store_matrix_sync(
            Cg + (size_t)(tr * 64 + rt * 16) * 256 + tc * 64 + cg * 32 + j * 16,
            acc[j], 256, wmma::mem_row_major);
}

// ---------------- K3: attention softmax (per b,h: 64x64), parallel ----------
// 256 threads. Softmax: 4 threads per row, 16 vk each, shfl group-reduce.
__global__ void k_attn() {
    int b = blockIdx.x / H_, h = blockIdx.x % H_;
    __shared__ float qh[64][33], kh[64][33], sc[64][65];
    int tid = threadIdx.x;   // 256 threads

    for (int i = tid; i < 64 * 32; i += 256) {
        int vq = i >> 5, d = i & 31;
        qh[vq][d] = g_q[(size_t)(b * 64 + vq) * D_ + h * 32 + d];
        kh[vq][d] = g_k[(size_t)(b * 64 + vq) * D_ + h * 32 + d];
    }
    __syncthreads();

    const float scale = rsqrtf((float)DH_);
    for (int i = tid; i < 64 * 64; i += 256) {
        int vq = i >> 6, vk = i & 63;
        float s = 0.0f;
#pragma unroll
        for (int d = 0; d < 32; d++) s += qh[vq][d] * kh[vk][d];
        sc[vq][vk] = s * scale;
    }
    __syncthreads();

    // 4 threads per row; thread s of row vq owns vk = s*16 .. s*16+15
    {
        int vq = tid >> 2, s = tid & 3;
        int v0 = s * 16;
        float e[16];
        float mx = -1e30f;
#pragma unroll
        for (int j = 0; j < 16; j++) { e[j] = sc[vq][v0 + j]; mx = fmaxf(mx, e[j]); }
        mx = fmaxf(mx, __shfl_xor_sync(0xffffffffu, mx, 1));
        mx = fmaxf(mx, __shfl_xor_sync(0xffffffffu, mx, 2));
        float sum = 0.0f;
#pragma unroll
        for (int j = 0; j < 16; j++) { e[j] = expf(e[j] - mx); sum += e[j]; }
        sum += __shfl_xor_sync(0xffffffffu, sum, 1);
        sum += __shfl_xor_sync(0xffffffffu, sum, 2);
        float inv = 1.0f / sum;
        __half* dst = g_attn + (size_t)((b * H_ + h) * 64 + vq) * 64 + v0;
#pragma unroll
        for (int j = 0; j < 8; j++) {
            __half2 hv = __floats2half2_rn(e[2 * j] * inv, e[2 * j + 1] * inv);
            *(__half2*)(dst + 2 * j) = hv;
        }
    }
}

// ---------------- k_main helpers ---------------------------------------------
// load one K=32 chunk: W[n=0..255][kc*32 .. +32) -> sW [256][LDW]
__device__ __forceinline__ void load_wchunk(__half* sW, const __half* __restrict__ Wg,
                                            int kc, int tid) {
#pragma unroll
    for (int i = 0; i < 2; i++) {
        int idx = tid + i * 512;            // 0..1023
        int n = idx >> 2, seg = idx & 3;
        cp16(sW + n * LDW + seg * 8, Wg + (size_t)n * 256 + kc * 32 + seg * 8);
    }
    cp_commit();
}

// C(128x256) = A(128x256 f16 in sA) @ W(256x256 f16)^T, f16 accumulate.
// 16 warps: rb = w>>2 (32 rows), cb = w&3 (64 cols). K=32 chunks, 2 buffers.
__device__ __forceinline__ void gemm_k256(const __half* __restrict__ Wg,
                                          const __half* sA,
                                          __half* sW0, __half* sW1,
                                          unsigned acc[2][8][2], int tid, int lane) {
    int w = tid >> 5, rb = w >> 2, cb = w & 3;
#pragma unroll
    for (int i = 0; i < 2; i++)
#pragma unroll
        for (int j = 0; j < 8; j++) { acc[i][j][0] = 0u; acc[i][j][1] = 0u; }

    int arow = lane & 15, acolb = (lane >> 4) << 3;
    int brow = (lane & 7) + ((lane & 16) ? 8 : 0), bcolb = (lane & 8) ? 8 : 0;

#pragma unroll
    for (int kc = 0; kc < 8; kc++) {
        const __half* cur = (kc & 1) ? sW1 : sW0;
        __half* nxt = (kc & 1) ? sW0 : sW1;
        if (kc < 7) { load_wchunk(nxt, Wg, kc + 1, tid); cp_wait<1>(); }
        else        { cp_wait<0>(); }
        __syncthreads();
#pragma unroll
        for (int s = 0; s < 2; s++) {
            int k0 = s * 16;
            unsigned a0[4], a1[4];
            ldsm_x4(a0, sA + (rb * 32 + arow) * LDA + kc * 32 + k0 + acolb);
            ldsm_x4(a1, sA + (rb * 32 + 16 + arow) * LDA + kc * 32 + k0 + acolb);
#pragma unroll
            for (int jj = 0; jj < 4; jj++) {
                unsigned bb[4];
                ldsm_x4(bb, cur + (cb * 64 + jj * 16 + brow) * LDW + k0 + bcolb);
                mma_f16(acc[0][jj * 2 + 0], a0, bb + 0);
                mma_f16(acc[0][jj * 2 + 1], a0, bb + 2);
                mma_f16(acc[1][jj * 2 + 0], a1, bb + 0);
                mma_f16(acc[1][jj * 2 + 1], a1, bb + 2);
            }
        }
        __syncthreads();
    }
}

// store f16 accumulators (packed half2) straight into sA
__device__ __forceinline__ void store_acc_f16(unsigned acc[2][8][2], __half* sA,
                                              int tid, int lane) {
    int w = tid >> 5, rb = w >> 2, cb = w & 3;
    int r0 = rb * 32 + (lane >> 2), c0 = cb * 64 + (lane & 3) * 2;
#pragma unroll
    for (int i = 0; i < 2; i++)
#pragma unroll
        for (int jj = 0; jj < 8; jj++) {
            *(unsigned*)(sA + (r0 + i * 16) * LDA + c0 + jj * 8) = acc[i][jj][0];
            *(unsigned*)(sA + (r0 + i * 16 + 8) * LDA + c0 + jj * 8) = acc[i][jj][1];
        }
}

// ---------------- K4: fused LN + V-GEMM + attn-mix + proj + residual ---------
__global__ void __launch_bounds__(512, 2)
k_main(const float* __restrict__ x, const float* __restrict__ lnw,
       const float* __restrict__ lnb, const float* __restrict__ bproj,
       float* __restrict__ out) {
    extern __shared__ char smem[];
    __half* sA  = (__half*)smem;                        // [128][LDA]
    __half* sW0 = (__half*)(smem + OFF_W0);             // [256][LDW]
    __half* sW1 = (__half*)(smem + OFF_W1);             // [256][LDW]

    int b = blockIdx.x / 129, tp = blockIdx.x % 129;
    int t0 = tp * 2;
    bool dup = (t0 == 256);
    int t1 = dup ? t0 : t0 + 1;
    int tid = threadIdx.x, w = tid >> 5, lane = tid & 31;

    // Wv chunk0 prefetch (hidden under LN)
    load_wchunk(sW0, g_wv16, 0, tid);

    // ---- LayerNorm: 128 rows -> sA f16 ----
    for (int r = w; r < 128; r += 16) {
        int t = (r < 64) ? t0 : t1;
        int v = r & 63;
        const float* rowp = x + ((size_t)(b * 64 + v) * T1_ + t) * D_ + lane * 8;
        float4 p0 = *(const float4*)rowp;
        float4 p1 = *(const float4*)(rowp + 4);
        float rr[8] = {p0.x, p0.y, p0.z, p0.w, p1.x, p1.y, p1.z, p1.w};
        float s = 0.0f;
#pragma unroll
        for (int j = 0; j < 8; j++) s += rr[j];
        s = warp_sum(s);
        float mu = s * (1.0f / 256.0f);
        float var = 0.0f;
#pragma unroll
        for (int j = 0; j < 8; j++) { float d = rr[j] - mu; var += d * d; }
        var = warp_sum(var);
        float rs = rsqrtf(var * (1.0f / 256.0f) + EPS);
        float4 w0 = *(const float4*)(lnw + lane * 8);
        float4 w1 = *(const float4*)(lnw + lane * 8 + 4);
        float4 b0 = *(const float4*)(lnb + lane * 8);
        float4 b1 = *(const float4*)(lnb + lane * 8 + 4);
        float lwv[8] = {w0.x, w0.y, w0.z, w0.w, w1.x, w1.y, w1.z, w1.w};
        float lbv[8] = {b0.x, b0.y, b0.z, b0.w, b1.x, b1.y, b1.z, b1.w};
#pragma unroll
        for (int j = 0; j < 4; j++) {
            float2 fv = make_float2(
                (rr[2 * j] - mu) * rs * lwv[2 * j] + lbv[2 * j],
                (rr[2 * j + 1] - mu) * rs * lwv[2 * j + 1] + lbv[2 * j + 1]);
            *(__half2*)(sA + r * LDA + lane * 8 + 2 * j) = __float22half2_rn(fv);
        }
    }
    __syncthreads();

    // ---- GEMM1: vf = xn @ Wv^T (f16 acc) ----
    {
        unsigned acc[2][8][2];
        gemm_k256(g_wv16, sA, sW0, sW1, acc, tid, lane);
        load_wchunk(sW0, g_wp16, 0, tid);   // prefetch Wp chunk0 (sW0 free)
        store_acc_f16(acc, sA, tid, lane);  // vf into sA (already f16)
    }
    __syncthreads();

    // ---- attn mixing: warp (tsub = w>>3, h = w&7), f16 HMMA ----
    {
        int tsub = w >> 3, h = w & 7;
        unsigned mc[4][4][2];
#pragma unroll
        for (int a = 0; a < 4; a++)
#pragma unroll
            for (int c = 0; c < 4; c++) { mc[a][c][0] = 0u; mc[a][c][1] = 0u; }

        const __half* att = g_attn + (size_t)(b * H_ + h) * 64 * 64;
        int lr = lane >> 2, lc = (lane & 3) * 2;
        int trow = lane & 15, tcolb = (lane & 16) ? 8 : 0;
#pragma unroll
        for (int kt = 0; kt < 4; kt++) {
            int k0 = kt * 16;
            unsigned bb0[4], bb1[4];
            ldsm_x4t(bb0, sA + (tsub * 64 + k0 + trow) * LDA + h * 32 + tcolb);
            ldsm_x4t(bb1, sA + (tsub * 64 + k0 + trow) * LDA + h * 32 + 16 + tcolb);
#pragma unroll
            for (int rt = 0; rt < 4; rt++) {
                const __half* ap = att + (size_t)(rt * 16 + lr) * 64 + k0 + lc;
                unsigned aa[4];
                aa[0] = *(const unsigned*)ap;
                aa[1] = *(const unsigned*)(ap + 8 * 64);
                aa[2] = *(const unsigned*)(ap + 8);
                aa[3] = *(const unsigned*)(ap + 8 * 64 + 8);
                mma_f16(mc[rt][0], aa, bb0 + 0);
                mma_f16(mc[rt][1], aa, bb0 + 2);
                mma_f16(mc[rt][2], aa, bb1 + 0);
                mma_f16(mc[rt][3], aa, bb1 + 2);
            }
        }
        // per-warp tile [tsub*64 rows][h*32 cols] is self-contained
        int r0 = tsub * 64 + (lane >> 2), c0 = h * 32 + (lane & 3) * 2;
#pragma unroll
        for (int rt = 0; rt < 4; rt++)
#pragma unroll
            for (int jj = 0; jj < 4; jj++) {
                *(unsigned*)(sA + (r0 + rt * 16) * LDA + c0 + jj * 8) = mc[rt][jj][0];
                *(unsigned*)(sA + (r0 + rt * 16 + 8) * LDA + c0 + jj * 8) = mc[rt][jj][1];
            }
    }
    __syncthreads();

    // ---- GEMM2: proj = mixed @ Wp^T (f16 acc), epilogue from registers ----
    {
        unsigned acc[2][8][2];
        gemm_k256(g_wp16, sA, sW0, sW1, acc, tid, lane);

        int rb = w >> 2, cb = w & 3;
        if (!(dup && rb >= 2)) {
            int r0 = rb * 32 + (lane >> 2), c0 = cb * 64 + (lane & 3) * 2;
#pragma unroll
            for (int i = 0; i < 2; i++)
#pragma unroll
                for (int half = 0; half < 2; half++) {
                    int rr = r0 + i * 16 + half * 8;
                    int v = rr & 63;
                    int t = (rr < 64) ? t0 : t1;
                    size_t base = ((size_t)(b * 64 + v) * T1_ + t) * D_;
#pragma unroll
                    for (int jj = 0; jj < 8; jj++) {
                        int c = c0 + jj * 8;
                        size_t gi = base + c;
                        float2 xv = *(const float2*)(x + gi);
                        float2 pv = __half22float2(
                            *(const __half2*)&acc[i][jj][half]);
                        float2 o;
                        o.x = pv.x + bproj[c] + xv.x;
                        o.y = pv.y + bproj[c + 1] + xv.y;
                        *(float2*)(out + gi) = o;
                    }
                }
        }
    }
}

// ---------------- launch ----------------------------------------------------
extern "C" void kernel_launch(void* const* d_in, const int* in_sizes, int n_in,
                              void* d_out, int out_size) {
    const float* x     = (const float*)d_in[0];
    const void*  mask  = d_in[1];
    const float* lnw   = (const float*)d_in[2];
    const float* lnb   = (const float*)d_in[3];
    const float* wqkv  = (const float*)d_in[4];
    const float* wproj = (const float*)d_in[5];
    const float* bproj = (const float*)d_in[6];
    float* out = (float*)d_out;

    cudaFuncSetAttribute(k_main, cudaFuncAttributeMaxDynamicSharedMemorySize, SM_MAIN);
    cudaFuncSetAttribute(k_qk, cudaFuncAttributeMaxDynamicSharedMemorySize, SM_QK);

    k_prep<<<576, 256>>>((const unsigned char*)mask, wqkv, wproj);
    k_xbar<<<B_ * V_, 256>>>(x, mask, lnw, lnb);
    k_qk<<<64, 256, SM_QK>>>();
    k_attn<<<B_ * H_, 256>>>();
    k_main<<<B_ * 129, 512, SM_MAIN>>>(x, lnw, lnb, bproj, out);
}